// round 3
// baseline (speedup 1.0000x reference)
#include <cuda_runtime.h>
#include <math.h>

#define BB 2
#define SEQ 2048
#define DIM 1024
#define HEADS 16
#define DHEAD 64
#define INNER 1024
#define MTOT (BB*SEQ)          // 4096
#define QKVN (3*INNER)         // 3072
#define ATT_SCALE 0.125f       // 64^-0.5
#define LNEPS 1e-5f
#define NEG_BIG -1.0e30f

// scratch (static device allocation is allowed)
__device__ float g_xn [(size_t)MTOT * DIM];    // 16 MB
__device__ float g_qkv[(size_t)MTOT * QKVN];   // 48 MB
__device__ float g_att[(size_t)MTOT * INNER];  // 16 MB

// ---------------------------------------------------------------------------
// LayerNorm: one block per row (4096 rows), 256 threads, float4 per thread.
// ---------------------------------------------------------------------------
__global__ __launch_bounds__(256) void ln_kernel(const float* __restrict__ x,
                                                 const float* __restrict__ gamma,
                                                 const float* __restrict__ beta) {
    int row = blockIdx.x;
    int t = threadIdx.x;
    const float4* xr = (const float4*)(x + (size_t)row * DIM);
    float4 v = xr[t];
    float s  = v.x + v.y + v.z + v.w;
    float ss = v.x*v.x + v.y*v.y + v.z*v.z + v.w*v.w;
    #pragma unroll
    for (int o = 16; o > 0; o >>= 1) {
        s  += __shfl_xor_sync(0xffffffffu, s,  o);
        ss += __shfl_xor_sync(0xffffffffu, ss, o);
    }
    __shared__ float rs[8], rss[8];
    __shared__ float s_mu, s_rstd;
    int wid = t >> 5, lane = t & 31;
    if (lane == 0) { rs[wid] = s; rss[wid] = ss; }
    __syncthreads();
    if (t == 0) {
        float ts = 0.f, tss = 0.f;
        #pragma unroll
        for (int i = 0; i < 8; i++) { ts += rs[i]; tss += rss[i]; }
        float mu  = ts * (1.0f / DIM);
        float var = tss * (1.0f / DIM) - mu * mu;
        s_mu = mu;
        s_rstd = rsqrtf(var + LNEPS);
    }
    __syncthreads();
    float mu = s_mu, rstd = s_rstd;
    float4 g = ((const float4*)gamma)[t];
    float4 b = ((const float4*)beta)[t];
    float4 o;
    o.x = (v.x - mu) * rstd * g.x + b.x;
    o.y = (v.y - mu) * rstd * g.y + b.y;
    o.z = (v.z - mu) * rstd * g.z + b.z;
    o.w = (v.w - mu) * rstd * g.w + b.w;
    ((float4*)(g_xn + (size_t)row * DIM))[t] = o;
}

// ---------------------------------------------------------------------------
// fp32 GEMM: C[M,Nn] = A[M,K] @ W[K,Nn].  BM=128, BN=64, BK=16, 256 threads,
// per-thread 8x4 register tile.
// ---------------------------------------------------------------------------
__global__ __launch_bounds__(256) void gemm_kernel(const float* __restrict__ A,
                                                   const float* __restrict__ W,
                                                   float* __restrict__ C,
                                                   int K, int Nn) {
    __shared__ float As[128][17];   // padded (17) to avoid bank conflicts
    __shared__ float Ws[16][64];

    int t  = threadIdx.x;
    int tx = t & 15;      // 0..15 -> 4 output cols
    int ty = t >> 4;      // 0..15 -> 8 output rows
    int m0 = blockIdx.y * 128;
    int n0 = blockIdx.x * 64;

    float acc[8][4];
    #pragma unroll
    for (int i = 0; i < 8; i++)
        #pragma unroll
        for (int j = 0; j < 4; j++) acc[i][j] = 0.f;

    for (int k0 = 0; k0 < K; k0 += 16) {
        // A tile: 128x16 = 512 float4, 2 per thread
        #pragma unroll
        for (int p = 0; p < 2; p++) {
            int idx = t + p * 256;
            int r = idx >> 2, kq = idx & 3;
            float4 a4 = *(const float4*)(A + (size_t)(m0 + r) * K + k0 + kq * 4);
            As[r][kq*4 + 0] = a4.x;
            As[r][kq*4 + 1] = a4.y;
            As[r][kq*4 + 2] = a4.z;
            As[r][kq*4 + 3] = a4.w;
        }
        // W tile: 16x64 = 256 float4, 1 per thread
        {
            int kk = t >> 4, cq = t & 15;
            float4 w4 = *(const float4*)(W + (size_t)(k0 + kk) * Nn + n0 + cq * 4);
            *(float4*)&Ws[kk][cq * 4] = w4;
        }
        __syncthreads();

        #pragma unroll
        for (int kk = 0; kk < 16; kk++) {
            float4 b4 = *(const float4*)&Ws[kk][tx * 4];
            #pragma unroll
            for (int i = 0; i < 8; i++) {
                float a = As[ty*8 + i][kk];
                acc[i][0] += a * b4.x;
                acc[i][1] += a * b4.y;
                acc[i][2] += a * b4.z;
                acc[i][3] += a * b4.w;
            }
        }
        __syncthreads();
    }

    #pragma unroll
    for (int i = 0; i < 8; i++) {
        float4 o = make_float4(acc[i][0], acc[i][1], acc[i][2], acc[i][3]);
        *(float4*)(C + (size_t)(m0 + ty*8 + i) * Nn + n0 + tx * 4) = o;
    }
}

// ---------------------------------------------------------------------------
// Flash-style attention with diagonal mask.
// Block = (qtile of 64 rows, head, batch). 256 threads.
// Thread (ty = t/16 -> 4 rows, tx = t%16 -> 4 cols) owns a 4x4 tile of S and O.
// K and V share one smem buffer (V loaded after S is computed).
// ---------------------------------------------------------------------------
#define ASTRIDE 68   // 64 + 4: keeps float4 alignment, scatters banks
#define ATT_SMEM (3 * 64 * ASTRIDE * 4)

__global__ __launch_bounds__(256) void attn_kernel(const float* __restrict__ qkv,
                                                   float* __restrict__ att) {
    extern __shared__ float sm[];
    float* Qs  = sm;                      // [64][ASTRIDE]
    float* KVs = sm + 64 * ASTRIDE;       // [64][ASTRIDE]  (K, then V)
    float* Ps  = sm + 2 * 64 * ASTRIDE;   // [64][ASTRIDE]

    int qt = blockIdx.x;           // 0..31
    int h  = blockIdx.y;           // 0..15
    int b  = blockIdx.z;           // 0..1
    int t  = threadIdx.x;
    int tx = t & 15;               // col group
    int ty = t >> 4;               // row group
    int qbase = qt * 64;

    // load Q tile [64][64]: 1024 float4, 4 per thread
    for (int i = t; i < 1024; i += 256) {
        int r = i >> 4, dq = i & 15;
        float4 v = *(const float4*)(qkv + (size_t)(b * SEQ + qbase + r) * QKVN
                                    + h * DHEAD + dq * 4);
        *(float4*)&Qs[r * ASTRIDE + dq * 4] = v;
    }

    float m_i[4], l_i[4], acc[4][4];
    #pragma unroll
    for (int i = 0; i < 4; i++) {
        m_i[i] = NEG_BIG; l_i[i] = 0.f;
        #pragma unroll
        for (int j = 0; j < 4; j++) acc[i][j] = 0.f;
    }

    for (int kt = 0; kt < SEQ / 64; kt++) {
        // load K tile into KVs
        for (int i = t; i < 1024; i += 256) {
            int r = i >> 4, dq = i & 15;
            float4 v = *(const float4*)(qkv + (size_t)(b * SEQ + kt * 64 + r) * QKVN
                                        + INNER + h * DHEAD + dq * 4);
            *(float4*)&KVs[r * ASTRIDE + dq * 4] = v;
        }
        __syncthreads();

        // S = Q K^T (4x4 per thread), float4 over d
        float s[4][4];
        #pragma unroll
        for (int i = 0; i < 4; i++)
            #pragma unroll
            for (int j = 0; j < 4; j++) s[i][j] = 0.f;

        #pragma unroll 4
        for (int d = 0; d < 64; d += 4) {
            float4 q4[4], k4[4];
            #pragma unroll
            for (int i = 0; i < 4; i++)
                q4[i] = *(const float4*)&Qs[(ty*4 + i) * ASTRIDE + d];
            #pragma unroll
            for (int j = 0; j < 4; j++)
                k4[j] = *(const float4*)&KVs[(tx*4 + j) * ASTRIDE + d];
            #pragma unroll
            for (int i = 0; i < 4; i++)
                #pragma unroll
                for (int j = 0; j < 4; j++)
                    s[i][j] += q4[i].x*k4[j].x + q4[i].y*k4[j].y
                             + q4[i].z*k4[j].z + q4[i].w*k4[j].w;
        }

        // scale + diagonal mask
        #pragma unroll
        for (int i = 0; i < 4; i++) {
            int qg = qbase + ty*4 + i;
            #pragma unroll
            for (int j = 0; j < 4; j++) {
                int kg = kt*64 + tx*4 + j;
                s[i][j] = (qg == kg) ? NEG_BIG : s[i][j] * ATT_SCALE;
            }
        }

        // online softmax: row reductions across the 16 tx lanes (same warp)
        float p[4][4], alpha[4];
        #pragma unroll
        for (int i = 0; i < 4; i++) {
            float rm = fmaxf(fmaxf(s[i][0], s[i][1]), fmaxf(s[i][2], s[i][3]));
            #pragma unroll
            for (int o = 8; o > 0; o >>= 1)
                rm = fmaxf(rm, __shfl_xor_sync(0xffffffffu, rm, o));
            float mn = fmaxf(m_i[i], rm);
            float rsum = 0.f;
            #pragma unroll
            for (int j = 0; j < 4; j++) {
                p[i][j] = __expf(s[i][j] - mn);
                rsum += p[i][j];
            }
            #pragma unroll
            for (int o = 8; o > 0; o >>= 1)
                rsum += __shfl_xor_sync(0xffffffffu, rsum, o);
            alpha[i] = __expf(m_i[i] - mn);
            l_i[i] = l_i[i] * alpha[i] + rsum;
            m_i[i] = mn;
            #pragma unroll
            for (int j = 0; j < 4; j++) acc[i][j] *= alpha[i];
        }

        __syncthreads();   // everyone done reading K

        // store P, load V into KVs (overwrite K)
        #pragma unroll
        for (int i = 0; i < 4; i++)
            *(float4*)&Ps[(ty*4 + i) * ASTRIDE + tx*4] =
                make_float4(p[i][0], p[i][1], p[i][2], p[i][3]);
        for (int i = t; i < 1024; i += 256) {
            int r = i >> 4, dq = i & 15;
            float4 v = *(const float4*)(qkv + (size_t)(b * SEQ + kt * 64 + r) * QKVN
                                        + 2*INNER + h * DHEAD + dq * 4);
            *(float4*)&KVs[r * ASTRIDE + dq * 4] = v;
        }
        __syncthreads();

        // O += P V   (4x4 per thread)
        #pragma unroll 4
        for (int c = 0; c < 64; c++) {
            float pv[4];
            #pragma unroll
            for (int i = 0; i < 4; i++) pv[i] = Ps[(ty*4 + i) * ASTRIDE + c];
            float4 v4 = *(const float4*)&KVs[c * ASTRIDE + tx*4];
            #pragma unroll
            for (int i = 0; i < 4; i++) {
                acc[i][0] += pv[i] * v4.x;
                acc[i][1] += pv[i] * v4.y;
                acc[i][2] += pv[i] * v4.z;
                acc[i][3] += pv[i] * v4.w;
            }
        }
        __syncthreads();   // before next tile's K overwrite
    }

    // write O / l -> att  [b n (h d)] layout
    #pragma unroll
    for (int i = 0; i < 4; i++) {
        float inv = 1.0f / l_i[i];
        float4 o = make_float4(acc[i][0]*inv, acc[i][1]*inv, acc[i][2]*inv, acc[i][3]*inv);
        *(float4*)(att + (size_t)(b * SEQ + qbase + ty*4 + i) * INNER
                   + h * DHEAD + tx*4) = o;
    }
}

// ---------------------------------------------------------------------------
extern "C" void kernel_launch(void* const* d_in, const int* in_sizes, int n_in,
                              void* d_out, int out_size) {
    const float* x     = (const float*)d_in[0];
    const float* gamma = (const float*)d_in[1];
    const float* beta  = (const float*)d_in[2];
    const float* w_qkv = (const float*)d_in[3];
    const float* w_out = (const float*)d_in[4];
    float* out = (float*)d_out;

    float *xn, *qkvb, *attb;
    cudaGetSymbolAddress((void**)&xn,   g_xn);
    cudaGetSymbolAddress((void**)&qkvb, g_qkv);
    cudaGetSymbolAddress((void**)&attb, g_att);

    static int smem_set = 0;
    if (!smem_set) {
        cudaFuncSetAttribute(attn_kernel,
                             cudaFuncAttributeMaxDynamicSharedMemorySize, ATT_SMEM);
        smem_set = 1;
    }

    // 1. LayerNorm
    ln_kernel<<<MTOT, 256>>>(x, gamma, beta);
    // 2. QKV projection: [4096,1024] @ [1024,3072]
    gemm_kernel<<<dim3(QKVN / 64, MTOT / 128), 256>>>(xn, w_qkv, qkvb, DIM, QKVN);
    // 3. attention
    attn_kernel<<<dim3(SEQ / 64, HEADS, BB), 256, ATT_SMEM>>>(qkvb, attb);
    // 4. out projection: [4096,1024] @ [1024,1024]
    gemm_kernel<<<dim3(INNER / 64, MTOT / 128), 256>>>(attb, w_out, out, DIM, INNER);
}

// round 5
// speedup vs baseline: 2.8696x; 2.8696x over previous
#include <cuda_runtime.h>
#include <math.h>

#define BB 2
#define SEQ 2048
#define DIM 1024
#define HEADS 16
#define DHEAD 64
#define INNER 1024
#define MTOT (BB*SEQ)          // 4096
#define QKVN (3*INNER)         // 3072
#define ATT_SCALE 0.125f
#define LNEPS 1e-5f
#define NEG_BIG -1.0e30f

// scratch
__device__ float g_xn [(size_t)MTOT * DIM];    // 16 MB
__device__ float g_qkv[(size_t)MTOT * QKVN];   // 48 MB
__device__ float g_att[(size_t)MTOT * INNER];  // 16 MB

// ---------------------------------------------------------------------------
// helpers
// ---------------------------------------------------------------------------
__device__ __forceinline__ unsigned f2tf(float x) {
    unsigned u;
    asm("cvt.rna.tf32.f32 %0, %1;" : "=r"(u) : "f"(x));
    return u;
}
__device__ __forceinline__ float tf2f(float x) {   // round f32 -> tf32, keep as float bits
    return __uint_as_float(f2tf(x));
}

// D += A(16x8 tf32, row) * B(8x8 tf32, col), fp32 accum
__device__ __forceinline__ void mma8(float& d0, float& d1, float& d2, float& d3,
                                     unsigned a0, unsigned a1, unsigned a2, unsigned a3,
                                     unsigned b0, unsigned b1) {
    asm volatile("mma.sync.aligned.m16n8k8.row.col.f32.tf32.tf32.f32 "
                 "{%0,%1,%2,%3},{%4,%5,%6,%7},{%8,%9},{%0,%1,%2,%3};"
                 : "+f"(d0), "+f"(d1), "+f"(d2), "+f"(d3)
                 : "r"(a0), "r"(a1), "r"(a2), "r"(a3), "r"(b0), "r"(b1));
}

// ---------------------------------------------------------------------------
// LayerNorm: one block per row, 256 threads, float4 per thread.
// ---------------------------------------------------------------------------
__global__ __launch_bounds__(256) void ln_kernel(const float* __restrict__ x,
                                                 const float* __restrict__ gamma,
                                                 const float* __restrict__ beta) {
    int row = blockIdx.x;
    int t = threadIdx.x;
    const float4* xr = (const float4*)(x + (size_t)row * DIM);
    float4 v = xr[t];
    float s  = v.x + v.y + v.z + v.w;
    float ss = v.x*v.x + v.y*v.y + v.z*v.z + v.w*v.w;
    #pragma unroll
    for (int o = 16; o > 0; o >>= 1) {
        s  += __shfl_xor_sync(0xffffffffu, s,  o);
        ss += __shfl_xor_sync(0xffffffffu, ss, o);
    }
    __shared__ float rs[8], rss[8];
    __shared__ float s_mu, s_rstd;
    int wid = t >> 5, lane = t & 31;
    if (lane == 0) { rs[wid] = s; rss[wid] = ss; }
    __syncthreads();
    if (t == 0) {
        float ts = 0.f, tss = 0.f;
        #pragma unroll
        for (int i = 0; i < 8; i++) { ts += rs[i]; tss += rss[i]; }
        float mu  = ts * (1.0f / DIM);
        float var = tss * (1.0f / DIM) - mu * mu;
        s_mu = mu;
        s_rstd = rsqrtf(var + LNEPS);
    }
    __syncthreads();
    float mu = s_mu, rstd = s_rstd;
    float4 g = ((const float4*)gamma)[t];
    float4 b = ((const float4*)beta)[t];
    float4 o;
    o.x = (v.x - mu) * rstd * g.x + b.x;
    o.y = (v.y - mu) * rstd * g.y + b.y;
    o.z = (v.z - mu) * rstd * g.z + b.z;
    o.w = (v.w - mu) * rstd * g.w + b.w;
    ((float4*)(g_xn + (size_t)row * DIM))[t] = o;
}

// ---------------------------------------------------------------------------
// tf32 tensor-core GEMM: C[M,N] = A[M,K] @ W[K,N]
// BM=128, BN=64, BK=16, 256 threads = 8 warps (4m x 2n), warp tile 32x32.
// Double-buffered smem + register prefetch of globals.
// ---------------------------------------------------------------------------
#define AS_STR 20   // 128 rows x 16 cols, pad -> conflict-free frag loads
#define BS_STR 72   // 16 rows x 64 cols, pad 8 -> conflict-free frag loads

__global__ __launch_bounds__(256) void gemm_tc(const float* __restrict__ A,
                                               const float* __restrict__ W,
                                               float* __restrict__ C,
                                               int K, int N) {
    __shared__ float As[2][128 * AS_STR];
    __shared__ float Bs[2][16 * BS_STR];

    int t = threadIdx.x, w = t >> 5, lane = t & 31;
    int g = lane >> 2, tig = lane & 3;
    int wm = w >> 1, wn = w & 1;                 // warp grid 4m x 2n
    int m0 = blockIdx.y * 128, n0 = blockIdx.x * 64;

    int ar = t >> 2, aq = (t & 3) * 4;           // A: rows ar / ar+64, col chunk aq
    int bk = t >> 4, bc = (t & 15) * 4;          // B: row bk, col chunk bc

    float acc[2][4][4];
    #pragma unroll
    for (int mt = 0; mt < 2; mt++)
        #pragma unroll
        for (int nt = 0; nt < 4; nt++)
            #pragma unroll
            for (int i = 0; i < 4; i++) acc[mt][nt][i] = 0.f;

    const float* Ap = A + (size_t)m0 * K;

    // prologue: tile 0
    float4 a40 = *(const float4*)(Ap + (size_t)ar * K + aq);
    float4 a41 = *(const float4*)(Ap + (size_t)(ar + 64) * K + aq);
    float4 b4  = *(const float4*)(W + (size_t)bk * N + n0 + bc);
    {
        float4 c0 = make_float4(tf2f(a40.x), tf2f(a40.y), tf2f(a40.z), tf2f(a40.w));
        float4 c1 = make_float4(tf2f(a41.x), tf2f(a41.y), tf2f(a41.z), tf2f(a41.w));
        float4 cb = make_float4(tf2f(b4.x),  tf2f(b4.y),  tf2f(b4.z),  tf2f(b4.w));
        *(float4*)&As[0][ar * AS_STR + aq] = c0;
        *(float4*)&As[0][(ar + 64) * AS_STR + aq] = c1;
        *(float4*)&Bs[0][bk * BS_STR + bc] = cb;
    }
    __syncthreads();

    int nk = K / 16;
    for (int kt = 0; kt < nk; kt++) {
        int cur = kt & 1;
        float4 na0, na1, nb;
        if (kt + 1 < nk) {
            int k0 = (kt + 1) * 16;
            na0 = *(const float4*)(Ap + (size_t)ar * K + k0 + aq);
            na1 = *(const float4*)(Ap + (size_t)(ar + 64) * K + k0 + aq);
            nb  = *(const float4*)(W + (size_t)(k0 + bk) * N + n0 + bc);
        }
        const float* as = As[cur];
        const float* bs = Bs[cur];
        #pragma unroll
        for (int ks = 0; ks < 2; ks++) {
            unsigned af[2][4], bf[4][2];
            #pragma unroll
            for (int mt = 0; mt < 2; mt++) {
                int rb = wm * 32 + mt * 16;
                af[mt][0] = __float_as_uint(as[(rb + g)     * AS_STR + ks * 8 + tig]);
                af[mt][1] = __float_as_uint(as[(rb + g + 8) * AS_STR + ks * 8 + tig]);
                af[mt][2] = __float_as_uint(as[(rb + g)     * AS_STR + ks * 8 + tig + 4]);
                af[mt][3] = __float_as_uint(as[(rb + g + 8) * AS_STR + ks * 8 + tig + 4]);
            }
            #pragma unroll
            for (int nt = 0; nt < 4; nt++) {
                int cb = wn * 32 + nt * 8 + g;
                bf[nt][0] = __float_as_uint(bs[(ks * 8 + tig)     * BS_STR + cb]);
                bf[nt][1] = __float_as_uint(bs[(ks * 8 + tig + 4) * BS_STR + cb]);
            }
            #pragma unroll
            for (int mt = 0; mt < 2; mt++)
                #pragma unroll
                for (int nt = 0; nt < 4; nt++)
                    mma8(acc[mt][nt][0], acc[mt][nt][1], acc[mt][nt][2], acc[mt][nt][3],
                         af[mt][0], af[mt][1], af[mt][2], af[mt][3],
                         bf[nt][0], bf[nt][1]);
        }
        if (kt + 1 < nk) {
            int nxt = cur ^ 1;
            float4 c0 = make_float4(tf2f(na0.x), tf2f(na0.y), tf2f(na0.z), tf2f(na0.w));
            float4 c1 = make_float4(tf2f(na1.x), tf2f(na1.y), tf2f(na1.z), tf2f(na1.w));
            float4 cb = make_float4(tf2f(nb.x),  tf2f(nb.y),  tf2f(nb.z),  tf2f(nb.w));
            *(float4*)&As[nxt][ar * AS_STR + aq] = c0;
            *(float4*)&As[nxt][(ar + 64) * AS_STR + aq] = c1;
            *(float4*)&Bs[nxt][bk * BS_STR + bc] = cb;
            __syncthreads();
        }
    }

    #pragma unroll
    for (int mt = 0; mt < 2; mt++)
        #pragma unroll
        for (int nt = 0; nt < 4; nt++) {
            int row = m0 + wm * 32 + mt * 16 + g;
            int col = n0 + wn * 32 + nt * 8 + 2 * tig;
            *(float2*)(C + (size_t)row * N + col) =
                make_float2(acc[mt][nt][0], acc[mt][nt][1]);
            *(float2*)(C + (size_t)(row + 8) * N + col) =
                make_float2(acc[mt][nt][2], acc[mt][nt][3]);
        }
}

// ---------------------------------------------------------------------------
// Flash attention, tf32 tensor cores.
// Block = 128 q-rows x (head, batch). 256 threads = 8 warps; warp owns 16 q-rows.
// Key loop over tiles of 64. S = Q K^T and O += P V via m16n8k8.
// Softmax rows live entirely within a lane-quad (shfl_xor 1,2).
// ---------------------------------------------------------------------------
#define KS_STR 72
#define VS_STR 76
#define PS_STR 72
#define ATT_SMEM_BYTES ((64*KS_STR + 64*VS_STR + 128*PS_STR) * 4)

__global__ __launch_bounds__(256) void attn_tc(const float* __restrict__ qkv,
                                               float* __restrict__ att) {
    extern __shared__ float sm[];
    float* Ks = sm;
    float* Vs = sm + 64 * KS_STR;
    float* Ps = sm + 64 * KS_STR + 64 * VS_STR;

    int t = threadIdx.x, w = t >> 5, lane = t & 31;
    int g = lane >> 2, tig = lane & 3;
    int qb = blockIdx.x * 128, h = blockIdx.y, b = blockIdx.z;
    const float* base = qkv + (size_t)b * SEQ * QKVN + h * DHEAD;

    // stage Q tile [128][64] into Ps
    for (int i = t; i < 2048; i += 256) {
        int r = i >> 4, q = (i & 15) * 4;
        float4 v = *(const float4*)(base + (size_t)(qb + r) * QKVN + q);
        *(float4*)&Ps[r * PS_STR + q] = v;
    }
    __syncthreads();

    int r0 = w * 16 + g, r1 = r0 + 8;
    unsigned qf[8][4];
    #pragma unroll
    for (int ks = 0; ks < 8; ks++) {
        qf[ks][0] = f2tf(Ps[r0 * PS_STR + ks * 8 + tig]);
        qf[ks][1] = f2tf(Ps[r1 * PS_STR + ks * 8 + tig]);
        qf[ks][2] = f2tf(Ps[r0 * PS_STR + ks * 8 + tig + 4]);
        qf[ks][3] = f2tf(Ps[r1 * PS_STR + ks * 8 + tig + 4]);
    }

    float o[8][4];
    #pragma unroll
    for (int nt = 0; nt < 8; nt++)
        #pragma unroll
        for (int i = 0; i < 4; i++) o[nt][i] = 0.f;
    float mr0 = NEG_BIG, mr1 = NEG_BIG, l0 = 0.f, l1 = 0.f;
    int qg0 = qb + w * 16 + g, qg1 = qg0 + 8;

    for (int kt = 0; kt < SEQ / 64; kt++) {
        __syncthreads();    // previous PV reads of Ks/Vs done
        // load K,V tiles (tf32-converted)
        for (int i = t; i < 1024; i += 256) {
            int r = i >> 4, q = (i & 15) * 4;
            const float* kp = base + (size_t)(kt * 64 + r) * QKVN + q;
            float4 kv = *(const float4*)(kp + INNER);
            float4 vv = *(const float4*)(kp + 2 * INNER);
            *(float4*)&Ks[r * KS_STR + q] =
                make_float4(tf2f(kv.x), tf2f(kv.y), tf2f(kv.z), tf2f(kv.w));
            *(float4*)&Vs[r * VS_STR + q] =
                make_float4(tf2f(vv.x), tf2f(vv.y), tf2f(vv.z), tf2f(vv.w));
        }
        __syncthreads();

        // S = Q K^T : warp's 16 rows x 64 keys
        float s[8][4];
        #pragma unroll
        for (int nt = 0; nt < 8; nt++) {
            s[nt][0] = s[nt][1] = s[nt][2] = s[nt][3] = 0.f;
            #pragma unroll
            for (int ks = 0; ks < 8; ks++) {
                unsigned b0 = __float_as_uint(Ks[(nt * 8 + g) * KS_STR + ks * 8 + tig]);
                unsigned b1 = __float_as_uint(Ks[(nt * 8 + g) * KS_STR + ks * 8 + tig + 4]);
                mma8(s[nt][0], s[nt][1], s[nt][2], s[nt][3],
                     qf[ks][0], qf[ks][1], qf[ks][2], qf[ks][3], b0, b1);
            }
        }

        // scale + diagonal mask
        #pragma unroll
        for (int nt = 0; nt < 8; nt++) {
            int c0 = kt * 64 + nt * 8 + 2 * tig, c1 = c0 + 1;
            s[nt][0] = (qg0 == c0) ? NEG_BIG : s[nt][0] * ATT_SCALE;
            s[nt][1] = (qg0 == c1) ? NEG_BIG : s[nt][1] * ATT_SCALE;
            s[nt][2] = (qg1 == c0) ? NEG_BIG : s[nt][2] * ATT_SCALE;
            s[nt][3] = (qg1 == c1) ? NEG_BIG : s[nt][3] * ATT_SCALE;
        }

        // online softmax (row g in c0/c1, row g+8 in c2/c3; reduce across quad)
        float rm0 = NEG_BIG, rm1 = NEG_BIG;
        #pragma unroll
        for (int nt = 0; nt < 8; nt++) {
            rm0 = fmaxf(rm0, fmaxf(s[nt][0], s[nt][1]));
            rm1 = fmaxf(rm1, fmaxf(s[nt][2], s[nt][3]));
        }
        #pragma unroll
        for (int off = 1; off <= 2; off <<= 1) {
            rm0 = fmaxf(rm0, __shfl_xor_sync(0xffffffffu, rm0, off));
            rm1 = fmaxf(rm1, __shfl_xor_sync(0xffffffffu, rm1, off));
        }
        float mn0 = fmaxf(mr0, rm0), mn1 = fmaxf(mr1, rm1);
        float sum0 = 0.f, sum1 = 0.f;
        #pragma unroll
        for (int nt = 0; nt < 8; nt++) {
            s[nt][0] = __expf(s[nt][0] - mn0);
            s[nt][1] = __expf(s[nt][1] - mn0);
            s[nt][2] = __expf(s[nt][2] - mn1);
            s[nt][3] = __expf(s[nt][3] - mn1);
            sum0 += s[nt][0] + s[nt][1];
            sum1 += s[nt][2] + s[nt][3];
        }
        #pragma unroll
        for (int off = 1; off <= 2; off <<= 1) {
            sum0 += __shfl_xor_sync(0xffffffffu, sum0, off);
            sum1 += __shfl_xor_sync(0xffffffffu, sum1, off);
        }
        float al0 = __expf(mr0 - mn0), al1 = __expf(mr1 - mn1);
        l0 = l0 * al0 + sum0;
        l1 = l1 * al1 + sum1;
        mr0 = mn0; mr1 = mn1;
        #pragma unroll
        for (int nt = 0; nt < 8; nt++) {
            o[nt][0] *= al0; o[nt][1] *= al0;
            o[nt][2] *= al1; o[nt][3] *= al1;
        }

        // store P (warp-private region of Ps), tf32-converted
        #pragma unroll
        for (int nt = 0; nt < 8; nt++) {
            *(float2*)&Ps[r0 * PS_STR + nt * 8 + 2 * tig] =
                make_float2(tf2f(s[nt][0]), tf2f(s[nt][1]));
            *(float2*)&Ps[r1 * PS_STR + nt * 8 + 2 * tig] =
                make_float2(tf2f(s[nt][2]), tf2f(s[nt][3]));
        }
        __syncwarp();

        // O += P V
        #pragma unroll
        for (int ks = 0; ks < 8; ks++) {
            unsigned a0 = __float_as_uint(Ps[r0 * PS_STR + ks * 8 + tig]);
            unsigned a1 = __float_as_uint(Ps[r1 * PS_STR + ks * 8 + tig]);
            unsigned a2 = __float_as_uint(Ps[r0 * PS_STR + ks * 8 + tig + 4]);
            unsigned a3 = __float_as_uint(Ps[r1 * PS_STR + ks * 8 + tig + 4]);
            #pragma unroll
            for (int nt = 0; nt < 8; nt++) {
                unsigned b0 = __float_as_uint(Vs[(ks * 8 + tig)     * VS_STR + nt * 8 + g]);
                unsigned b1 = __float_as_uint(Vs[(ks * 8 + tig + 4) * VS_STR + nt * 8 + g]);
                mma8(o[nt][0], o[nt][1], o[nt][2], o[nt][3], a0, a1, a2, a3, b0, b1);
            }
        }
    }

    float i0 = 1.0f / l0, i1 = 1.0f / l1;
    #pragma unroll
    for (int nt = 0; nt < 8; nt++) {
        int col = h * DHEAD + nt * 8 + 2 * tig;
        *(float2*)(att + (size_t)(b * SEQ + qg0) * INNER + col) =
            make_float2(o[nt][0] * i0, o[nt][1] * i0);
        *(float2*)(att + (size_t)(b * SEQ + qg1) * INNER + col) =
            make_float2(o[nt][2] * i1, o[nt][3] * i1);
    }
}

// ---------------------------------------------------------------------------
extern "C" void kernel_launch(void* const* d_in, const int* in_sizes, int n_in,
                              void* d_out, int out_size) {
    const float* x     = (const float*)d_in[0];
    const float* gamma = (const float*)d_in[1];
    const float* beta  = (const float*)d_in[2];
    const float* w_qkv = (const float*)d_in[3];
    const float* w_out = (const float*)d_in[4];
    float* out = (float*)d_out;

    float *xn, *qkvb, *attb;
    cudaGetSymbolAddress((void**)&xn,   g_xn);
    cudaGetSymbolAddress((void**)&qkvb, g_qkv);
    cudaGetSymbolAddress((void**)&attb, g_att);

    cudaFuncSetAttribute(attn_tc, cudaFuncAttributeMaxDynamicSharedMemorySize,
                         ATT_SMEM_BYTES);

    ln_kernel<<<MTOT, 256>>>(x, gamma, beta);
    gemm_tc<<<dim3(QKVN / 64, MTOT / 128), 256>>>(xn, w_qkv, qkvb, DIM, QKVN);
    attn_tc<<<dim3(SEQ / 128, HEADS, BB), 256, ATT_SMEM_BYTES>>>(qkvb, attb);
    gemm_tc<<<dim3(INNER / 64, MTOT / 128), 256>>>(attb, w_out, out, DIM, INNER);
}